// round 12
// baseline (speedup 1.0000x reference)
#include <cuda_runtime.h>
#include <cuda_bf16.h>
#include <math.h>
#include <stdint.h>

// Problem constants
#define NB   32
#define CC   256
#define HH   56
#define WW   56
#define HWP  3136      // 56*56
#define CHW  802816    // 256*3136
#define XPAD 512       // guard rows (128B each) at both ends of g_x arrays

// ---------------------------------------------------------------------------
// Device-global scratch (no allocation).
// g_x{h,l}: x as bf16 hi/lo, rows [(n*4+cb)*HWP + q + XPAD] of 64 ci,
//           128B rows, 16B chunk ch stored at position ch ^ (q&7).
// g_W{h,l}: weights as rows [(tap*4+cb)*256 + co] of 64 ci, chunk ^ (co&7).
// ---------------------------------------------------------------------------
#define XROWS ((size_t)NB * 4 * HWP + 2 * XPAD)
__device__ __align__(128) __nv_bfloat16 g_xh[XROWS * 64];
__device__ __align__(128) __nv_bfloat16 g_xl[XROWS * 64];
__device__ __align__(128) __nv_bfloat16 g_Wh[25 * 4 * 256 * 64];
__device__ __align__(128) __nv_bfloat16 g_Wl[25 * 4 * 256 * 64];
__device__ float g_t1[NB * CC * HH];      // max over W
__device__ float g_t9[NB * HH * WW];      // softmax weights

// ---------------------------------------------------------------------------
// Helpers
// ---------------------------------------------------------------------------
__device__ __forceinline__ uint32_t smem_u32(const void* p) {
    uint32_t a;
    asm("{ .reg .u64 t; cvta.to.shared.u64 t, %1; cvt.u32.u64 %0, t; }" : "=r"(a) : "l"(p));
    return a;
}

__device__ __forceinline__ void split1(float v, __nv_bfloat16& h, __nv_bfloat16& l) {
    h = __float2bfloat16(v);
    l = __float2bfloat16(v - __bfloat162float(h));
}

__device__ __forceinline__ void split2(float a, float b, uint32_t& hw, uint32_t& lw) {
    __nv_bfloat16 h0, l0, h1, l1;
    split1(a, h0, l0); split1(b, h1, l1);
    hw = (uint32_t)__bfloat16_as_ushort(h0) | ((uint32_t)__bfloat16_as_ushort(h1) << 16);
    lw = (uint32_t)__bfloat16_as_ushort(l0) | ((uint32_t)__bfloat16_as_ushort(l1) << 16);
}

__device__ __forceinline__ void mma16816(float* d, const uint32_t* a, const uint32_t* b) {
    asm volatile("mma.sync.aligned.m16n8k16.row.col.f32.bf16.bf16.f32 "
        "{%0,%1,%2,%3}, {%4,%5,%6,%7}, {%8,%9}, {%0,%1,%2,%3};"
        : "+f"(d[0]), "+f"(d[1]), "+f"(d[2]), "+f"(d[3])
        : "r"(a[0]), "r"(a[1]), "r"(a[2]), "r"(a[3]), "r"(b[0]), "r"(b[1]));
}

#define LDSM4(r, a)                                                              \
    asm volatile("ldmatrix.sync.aligned.m8n8.x4.shared.b16 {%0,%1,%2,%3}, [%4];" \
        : "=r"((r)[0]), "=r"((r)[1]), "=r"((r)[2]), "=r"((r)[3]) : "r"(a))

#define CPA16(d, s) \
    asm volatile("cp.async.cg.shared.global [%0], [%1], 16;" :: "r"(d), "l"(s) : "memory")

// cp.async with src-size: z==0 -> pure zero-fill of the 16B destination
#define CPA16Z(d, s, z) \
    asm volatile("cp.async.cg.shared.global [%0], [%1], 16, %2;" :: "r"(d), "l"(s), "r"(z) : "memory")

// ---------------------------------------------------------------------------
// 1) Weight split+relayout
// ---------------------------------------------------------------------------
__global__ void split_w_kernel(const float* __restrict__ w7) {
    int idx = blockIdx.x * 256 + threadIdx.x;   // 25*4*256*64 = 1,638,400 exact
    int cl  = idx & 63;
    int co  = (idx >> 6) & 255;
    int cb  = (idx >> 14) & 3;
    int tap = idx >> 16;
    float v = w7[co * 6400 + (cb * 64 + cl) * 25 + tap];
    __nv_bfloat16 h, l;
    split1(v, h, l);
    int ch = cl >> 3, wi = cl & 7;
    size_t dst = ((size_t)((tap * 4 + cb) * 256 + co)) * 64 + ((ch ^ (co & 7)) << 3) + wi;
    g_Wh[dst] = h; g_Wl[dst] = l;
}

// ---------------------------------------------------------------------------
// 2) x split+transpose: [n][c][p] -> hi/lo rows [(n*4+cb)*HWP + q + XPAD][64ci]
// ---------------------------------------------------------------------------
__global__ void split_x_kernel(const float* __restrict__ x) {
    __shared__ float tile[64][33];
    int n = blockIdx.z, cb = blockIdx.y;
    int q0t = blockIdx.x * 32;
    int tid = threadIdx.x;
    int ln = tid & 31;
    #pragma unroll
    for (int i = 0; i < 8; i++) {
        int cl = (tid >> 5) + i * 8;
        tile[cl][ln] = x[n * CHW + (cb * 64 + cl) * HWP + q0t + ln];
    }
    __syncthreads();
    int ql = tid >> 3, ch = tid & 7;
    int q = q0t + ql;
    int chs = ch ^ (q & 7);
    uint32_t hw[4], lw[4];
    #pragma unroll
    for (int j = 0; j < 4; j++)
        split2(tile[ch * 8 + j * 2][ql], tile[ch * 8 + j * 2 + 1][ql], hw[j], lw[j]);
    size_t r16 = ((size_t)(n * 4 + cb) * HWP + q + XPAD) * 8 + chs;
    ((uint4*)g_xh)[r16] = make_uint4(hw[0], hw[1], hw[2], hw[3]);
    ((uint4*)g_xl)[r16] = make_uint4(lw[0], lw[1], lw[2], lw[3]);
}

// ---------------------------------------------------------------------------
// 3) t1 = max over W
// ---------------------------------------------------------------------------
__global__ void rowmax_kernel(const float* __restrict__ x) {
    int row  = blockIdx.x * 4 + (threadIdx.x >> 5);
    int lane = threadIdx.x & 31;
    const float* xr = x + row * 56;
    float m = xr[lane];
    if (lane < 24) m = fmaxf(m, xr[lane + 32]);
    #pragma unroll
    for (int o = 16; o > 0; o >>= 1)
        m = fmaxf(m, __shfl_xor_sync(0xffffffffu, m, o));
    if (lane == 0) g_t1[row] = m;
}

// ---------------------------------------------------------------------------
// 4) t9 = softmax_w( sum_c tanh(relu(x)) * w6[c] ); 4 h-rows per 256-thr block
// ---------------------------------------------------------------------------
__global__ void softmax_kernel(const float* __restrict__ x,
                               const float* __restrict__ w6) {
    __shared__ float w6s[256];
    __shared__ float red[4][64];
    int n = blockIdx.y;
    int g = threadIdx.x >> 6, t = threadIdx.x & 63;
    int h = blockIdx.x * 4 + g;
    w6s[threadIdx.x] = w6[threadIdx.x];
    __syncthreads();

    float acc = 0.f;
    if (t < 56) {
        const float* xp = x + (n * 256 * 56 + h) * 56 + t;
        #pragma unroll 4
        for (int c = 0; c < 256; c++) {
            float v = xp[c * HWP];
            float r = fmaxf(v, 0.f);
            float th;
            asm("tanh.approx.f32 %0, %1;" : "=f"(th) : "f"(r));
            acc += th * w6s[c];
        }
    }
    red[g][t] = (t < 56) ? acc : -INFINITY;
    __syncthreads();
    #pragma unroll
    for (int s = 32; s > 0; s >>= 1) {
        if (t < s) red[g][t] = fmaxf(red[g][t], red[g][t + s]);
        __syncthreads();
    }
    float mx = red[g][0];
    __syncthreads();
    float e = (t < 56) ? expf(acc - mx) : 0.f;
    red[g][t] = e;
    __syncthreads();
    #pragma unroll
    for (int s = 32; s > 0; s >>= 1) {
        if (t < s) red[g][t] += red[g][t + s];
        __syncthreads();
    }
    float inv = 1.0f / red[g][0];
    if (t < 56) g_t9[(n * 56 + h) * 56 + t] = e * inv;
}

// ---------------------------------------------------------------------------
// 5) Conv via mma.sync implicit GEMM, bf16 split (hh+hl+lh), fused epilogue.
//    CTA: 256 co x 128 px; 8 warps (4M x 2N), warp tile 64x64.
//    SMEM buf b at b*98304: Ah 32K | Al 32K | Bh 16K | Bl 16K.
// ---------------------------------------------------------------------------
#define BUFSZ 98304u
#define SMEM_CONV (2 * 98304)

__global__ __launch_bounds__(256, 1)
void conv_hmma_kernel(const float* __restrict__ x, float* __restrict__ out) {
    extern __shared__ __align__(128) char sm[];
    const uint32_t smb = smem_u32(sm);
    const int tid = threadIdx.x, lane = tid & 31, wid = tid >> 5;
    const int n = blockIdx.y, p0 = blockIdx.x * 128;
    const int m0 = (wid & 3) * 64, n0w = (wid >> 2) * 64;

    // ldmatrix per-lane geometry (identical to the validated R11 mapping)
    const int a_row = ((lane >> 3) & 1) * 8 + (lane & 7);
    const int a_ks  = lane >> 4;
    const int b_row = ((lane >> 4) & 1) * 8 + (lane & 7);
    const int b_ks  = (lane >> 3) & 1;
    const int akey  = lane & 7;

    // staging geometry for B (row validity -> zfill)
    const int sr = tid >> 1, shalf = tid & 1;
    const int sp = p0 + sr;
    const int sh = sp / 56, sw = sp - sh * 56;

    float acc[4][8][4];
    #pragma unroll
    for (int i = 0; i < 4; i++)
        #pragma unroll
        for (int j = 0; j < 8; j++)
            #pragma unroll
            for (int k = 0; k < 4; k++) acc[i][j][k] = 0.f;

    auto issue = [&](int c) {
        int tap = c >> 2, cb = c & 3;
        int dh = (tap / 5) * 3 - 6, dw = (tap % 5) * 3 - 6;
        long long q0 = (long long)p0 + dh * 56 + dw;
        uint32_t dst = smb + (uint32_t)(c & 1) * BUFSZ;

        // A: contiguous 32KB hi + 32KB lo (256 rows x 128B), 128B per thread
        const char* ah = (const char*)g_Wh + ((size_t)((tap * 4 + cb) * 256)) * 128 + tid * 128;
        const char* al = (const char*)g_Wl + ((size_t)((tap * 4 + cb) * 256)) * 128 + tid * 128;
        uint32_t ad = dst + (uint32_t)tid * 128u;
        #pragma unroll
        for (int j = 0; j < 8; j++) {
            CPA16(ad + j * 16,           ah + j * 16);
            CPA16(ad + 32768u + j * 16,  al + j * 16);
        }

        // B: 128 rows x 128B hi/lo; 64B per thread; invalid rows -> zfill
        int ih = sh + dh, iw = sw + dw;
        uint32_t ssz = ((sp < HWP) && ((unsigned)ih < 56u) && ((unsigned)iw < 56u)) ? 16u : 0u;
        const char* bh = (const char*)g_xh +
            (size_t)((long long)(n * 4 + cb) * HWP + q0 + sr + XPAD) * 128 + shalf * 64;
        const char* bl = (const char*)g_xl +
            (size_t)((long long)(n * 4 + cb) * HWP + q0 + sr + XPAD) * 128 + shalf * 64;
        uint32_t bd = dst + 65536u + (uint32_t)sr * 128u + (uint32_t)shalf * 64u;
        #pragma unroll
        for (int j = 0; j < 4; j++) {
            CPA16Z(bd + j * 16,           bh + j * 16, ssz);
            CPA16Z(bd + 16384u + j * 16,  bl + j * 16, ssz);
        }
        asm volatile("cp.async.commit_group;" ::: "memory");
    };

    issue(0);

    for (int c = 0; c < 100; c++) {
        const uint32_t buf = smb + (uint32_t)(c & 1) * BUFSZ;
        const int tap = c >> 2;
        const int dh = (tap / 5) * 3 - 6, dw = (tap % 5) * 3 - 6;
        const int q0m = ((p0 + dh * 56 + dw) % 8 + 8) & 7;
        const int bkey = (q0m + b_row) & 7;

        if (c + 1 < 100) {
            issue(c + 1);
            asm volatile("cp.async.wait_group 1;" ::: "memory");
        } else {
            asm volatile("cp.async.wait_group 0;" ::: "memory");
        }
        __syncthreads();

        #pragma unroll
        for (int ks = 0; ks < 4; ks++) {
            uint32_t ah[4][4], al[4][4];
            #pragma unroll
            for (int mi = 0; mi < 4; mi++) {
                uint32_t ad = buf + (uint32_t)((m0 + mi * 16 + a_row) * 128)
                                  + (uint32_t)(((ks * 2 + a_ks) ^ akey) << 4);
                LDSM4(ah[mi], ad);
                LDSM4(al[mi], ad + 32768u);
            }
            #pragma unroll
            for (int nj = 0; nj < 4; nj++) {
                uint32_t bd = buf + 65536u + (uint32_t)((n0w + nj * 16 + b_row) * 128)
                                  + (uint32_t)(((ks * 2 + b_ks) ^ bkey) << 4);
                uint32_t bh4[4], bl4[4];
                LDSM4(bh4, bd);
                LDSM4(bl4, bd + 16384u);
                #pragma unroll
                for (int mi = 0; mi < 4; mi++) {
                    mma16816(acc[mi][nj * 2],     ah[mi], &bh4[0]);
                    mma16816(acc[mi][nj * 2 + 1], ah[mi], &bh4[2]);
                    mma16816(acc[mi][nj * 2],     ah[mi], &bl4[0]);
                    mma16816(acc[mi][nj * 2 + 1], ah[mi], &bl4[2]);
                    mma16816(acc[mi][nj * 2],     al[mi], &bh4[0]);
                    mma16816(acc[mi][nj * 2 + 1], al[mi], &bh4[2]);
                }
            }
        }
        __syncthreads();
    }

    // ---- fused epilogue: out = t1 - (t9*roll(x) + x*t7) ----
    const int er = lane >> 2, ec = (lane & 3) * 2;
    const float* xn = x + n * CHW;
    #pragma unroll
    for (int mi = 0; mi < 4; mi++) {
        #pragma unroll
        for (int rr = 0; rr < 2; rr++) {
            int co = m0 + mi * 16 + rr * 8 + er;
            const float* xc  = xn + co * HWP;
            const float* t1r = g_t1 + (n * 256 + co) * 56;
            float* oc = out + (n * 256 + co) * HWP;
            #pragma unroll
            for (int ng = 0; ng < 8; ng++) {
                #pragma unroll
                for (int e = 0; e < 2; e++) {
                    int p = p0 + n0w + ng * 8 + ec + e;
                    if (p < HWP) {
                        int h = p / 56, w = p - h * 56;
                        int hr = h - 2; if (hr < 0) hr += 56;
                        float dv  = acc[mi][ng][rr * 2 + e];
                        float xv  = xc[p];
                        float xrl = xc[hr * 56 + w];
                        oc[p] = t1r[h] - (g_t9[n * HWP + p] * xrl + xv * dv);
                    }
                }
            }
        }
    }
}

// ---------------------------------------------------------------------------
extern "C" void kernel_launch(void* const* d_in, const int* in_sizes, int n_in,
                              void* d_out, int out_size) {
    const float* x  = (const float*)d_in[0];
    const float* w6 = (const float*)d_in[1];
    const float* w7 = (const float*)d_in[2];
    float* out = (float*)d_out;

    cudaFuncSetAttribute(conv_hmma_kernel,
                         cudaFuncAttributeMaxDynamicSharedMemorySize, SMEM_CONV);

    split_w_kernel<<<25 * 4 * 256 * 64 / 256, 256>>>(w7);
    split_x_kernel<<<dim3(HWP / 32, 4, NB), 256>>>(x);
    rowmax_kernel<<<NB * CC * HH / 4, 128>>>(x);
    softmax_kernel<<<dim3(HH / 4, NB), 256>>>(x, w6);
    conv_hmma_kernel<<<dim3(25, NB), 256, SMEM_CONV>>>(x, out);
}

// round 13
// speedup vs baseline: 1.0105x; 1.0105x over previous
#include <cuda_runtime.h>
#include <cuda_bf16.h>
#include <math.h>
#include <stdint.h>

// Problem constants
#define NB   32
#define CC   256
#define HH   56
#define WW   56
#define HWP  3136      // 56*56
#define CHW  802816    // 256*3136
#define XPAD 512       // guard rows (256B each) around g_xt

// ---------------------------------------------------------------------------
// Device-global scratch (no allocation).
// g_xt: x as tf32, fragment-pair layout: row r = (n*4+cb)*HWP + q + XPAD,
//       256B/row = 32 slots x 8B. Slot s (s>>2 = (ks+q)&7, j = s&3) holds the
//       pair (ci = ks*8+j, ci+4) for k-step ks.  -> B frag = one LDS.64.
// g_Wt: weights tf32 in A-fragment order:
//       [tap][cb][mt(16 over 256 co)][ks(8)][lane(32)][4 x b32]
//       lane's 4 values: (r,k),(r+8,k),(r,k+4),(r+8,k+4),
//       r = mt*16 + (lane>>2), k = ks*8 + (lane&3). -> A frag = one LDS.128.
// ---------------------------------------------------------------------------
#define XROWS ((size_t)NB * 4 * HWP + 2 * XPAD)
__device__ __align__(128) uint32_t g_xt[XROWS * 64];
__device__ __align__(128) uint32_t g_Wt[25 * 4 * 16 * 8 * 32 * 4];
__device__ float g_t1[NB * CC * HH];      // max over W
__device__ float g_t9[NB * HH * WW];      // softmax weights

// ---------------------------------------------------------------------------
// Helpers
// ---------------------------------------------------------------------------
__device__ __forceinline__ uint32_t smem_u32(const void* p) {
    uint32_t a;
    asm("{ .reg .u64 t; cvta.to.shared.u64 t, %1; cvt.u32.u64 %0, t; }" : "=r"(a) : "l"(p));
    return a;
}

__device__ __forceinline__ uint32_t f2tf32(float f) {
    uint32_t u;
    asm("cvt.rna.tf32.f32 %0, %1;" : "=r"(u) : "f"(f));
    return u;
}

__device__ __forceinline__ void mma_tf32(float* d, const uint32_t* a, const uint32_t* b) {
    asm volatile("mma.sync.aligned.m16n8k8.row.col.f32.tf32.tf32.f32 "
        "{%0,%1,%2,%3}, {%4,%5,%6,%7}, {%8,%9}, {%0,%1,%2,%3};"
        : "+f"(d[0]), "+f"(d[1]), "+f"(d[2]), "+f"(d[3])
        : "r"(a[0]), "r"(a[1]), "r"(a[2]), "r"(a[3]), "r"(b[0]), "r"(b[1]));
}

#define LDS128(r, a)                                                       \
    asm volatile("ld.shared.v4.b32 {%0,%1,%2,%3}, [%4];"                   \
        : "=r"((r)[0]), "=r"((r)[1]), "=r"((r)[2]), "=r"((r)[3]) : "r"(a))

#define LDS64(r, a)                                                        \
    asm volatile("ld.shared.v2.b32 {%0,%1}, [%2];"                         \
        : "=r"((r)[0]), "=r"((r)[1]) : "r"(a))

#define CPA16(d, s) \
    asm volatile("cp.async.cg.shared.global [%0], [%1], 16;" :: "r"(d), "l"(s) : "memory")

// cp.async with src-size: z==0 -> pure zero-fill of the 16B destination
#define CPA16Z(d, s, z) \
    asm volatile("cp.async.cg.shared.global [%0], [%1], 16, %2;" :: "r"(d), "l"(s), "r"(z) : "memory")

// ---------------------------------------------------------------------------
// 1) Weight relayout into A-fragment order (tf32).
//    One thread per (tap, cb, mt, ks, lane) -> 4 values (16B).
// ---------------------------------------------------------------------------
__global__ void split_w_kernel(const float* __restrict__ w7) {
    int idx  = blockIdx.x * 256 + threadIdx.x;   // 25*4*16*8*32 = 409,600 exact
    int lane = idx & 31;
    int ks   = (idx >> 5) & 7;
    int mt   = (idx >> 8) & 15;
    int cb   = (idx >> 12) & 3;
    int tap  = idx >> 14;
    int r  = mt * 16 + (lane >> 2);
    int k  = ks * 8 + (lane & 3);
    int ci = cb * 64 + k;
    uint32_t v0 = f2tf32(w7[r * 6400 + ci * 25 + tap]);
    uint32_t v1 = f2tf32(w7[(r + 8) * 6400 + ci * 25 + tap]);
    uint32_t v2 = f2tf32(w7[r * 6400 + (ci + 4) * 25 + tap]);
    uint32_t v3 = f2tf32(w7[(r + 8) * 6400 + (ci + 4) * 25 + tap]);
    ((uint4*)g_Wt)[idx] = make_uint4(v0, v1, v2, v3);
}

// ---------------------------------------------------------------------------
// 2) x relayout: [n][c][q] -> g_xt rows (pair layout with (ks+q)&7 rotation)
// ---------------------------------------------------------------------------
__global__ void split_x_kernel(const float* __restrict__ x) {
    __shared__ float tile[64][33];
    int n = blockIdx.z, cb = blockIdx.y;
    int q0t = blockIdx.x * 32;
    int tid = threadIdx.x;
    int ln = tid & 31;
    #pragma unroll
    for (int i = 0; i < 8; i++) {
        int cl = (tid >> 5) + i * 8;
        tile[cl][ln] = x[n * CHW + (cb * 64 + cl) * HWP + q0t + ln];
    }
    __syncthreads();
    // thread -> (q-local 0..31, slot-group 0..7); writes 4 slots = 32B
    int ql = tid >> 3, sg = tid & 7;
    int q = q0t + ql;
    int ks = (sg - q) & 7;          // slot group sg holds k-step ks = (sg - q) mod 8
    uint32_t v[8];
    #pragma unroll
    for (int j = 0; j < 4; j++) {
        v[j * 2]     = f2tf32(tile[ks * 8 + j][ql]);
        v[j * 2 + 1] = f2tf32(tile[ks * 8 + j + 4][ql]);
    }
    size_t row = (size_t)(n * 4 + cb) * HWP + q + XPAD;
    uint4* dst = (uint4*)(g_xt + row * 64 + sg * 8);
    dst[0] = make_uint4(v[0], v[1], v[2], v[3]);
    dst[1] = make_uint4(v[4], v[5], v[6], v[7]);
}

// ---------------------------------------------------------------------------
// 3) t1 = max over W
// ---------------------------------------------------------------------------
__global__ void rowmax_kernel(const float* __restrict__ x) {
    int row  = blockIdx.x * 4 + (threadIdx.x >> 5);
    int lane = threadIdx.x & 31;
    const float* xr = x + row * 56;
    float m = xr[lane];
    if (lane < 24) m = fmaxf(m, xr[lane + 32]);
    #pragma unroll
    for (int o = 16; o > 0; o >>= 1)
        m = fmaxf(m, __shfl_xor_sync(0xffffffffu, m, o));
    if (lane == 0) g_t1[row] = m;
}

// ---------------------------------------------------------------------------
// 4) t9 = softmax_w( sum_c tanh(relu(x)) * w6[c] ); 4 h-rows per 256-thr block
// ---------------------------------------------------------------------------
__global__ void softmax_kernel(const float* __restrict__ x,
                               const float* __restrict__ w6) {
    __shared__ float w6s[256];
    __shared__ float red[4][64];
    int n = blockIdx.y;
    int g = threadIdx.x >> 6, t = threadIdx.x & 63;
    int h = blockIdx.x * 4 + g;
    w6s[threadIdx.x] = w6[threadIdx.x];
    __syncthreads();

    float acc = 0.f;
    if (t < 56) {
        const float* xp = x + (n * 256 * 56 + h) * 56 + t;
        #pragma unroll 4
        for (int c = 0; c < 256; c++) {
            float v = xp[c * HWP];
            float r = fmaxf(v, 0.f);
            float th;
            asm("tanh.approx.f32 %0, %1;" : "=f"(th) : "f"(r));
            acc += th * w6s[c];
        }
    }
    red[g][t] = (t < 56) ? acc : -INFINITY;
    __syncthreads();
    #pragma unroll
    for (int s = 32; s > 0; s >>= 1) {
        if (t < s) red[g][t] = fmaxf(red[g][t], red[g][t + s]);
        __syncthreads();
    }
    float mx = red[g][0];
    __syncthreads();
    float e = (t < 56) ? expf(acc - mx) : 0.f;
    red[g][t] = e;
    __syncthreads();
    #pragma unroll
    for (int s = 32; s > 0; s >>= 1) {
        if (t < s) red[g][t] += red[g][t + s];
        __syncthreads();
    }
    float inv = 1.0f / red[g][0];
    if (t < 56) g_t9[(n * 56 + h) * 56 + t] = e * inv;
}

// ---------------------------------------------------------------------------
// 5) Conv via mma.sync.m16n8k8.tf32 implicit GEMM (1 pass), fused epilogue.
//    CTA: 128 co x 128 px; 8 warps (4M x 2N), warp tile 32x64.
//    SMEM buf b at b*65536: A 32K (frag order) | B 32K (pair rows).
// ---------------------------------------------------------------------------
#define BUFSZ 65536u
#define SMEM_CONV (2 * 65536)

__global__ __launch_bounds__(256, 1)
void conv_tf32_kernel(const float* __restrict__ x, float* __restrict__ out) {
    extern __shared__ __align__(128) char sm[];
    const uint32_t smb = smem_u32(sm);
    const int tid = threadIdx.x, lane = tid & 31, wid = tid >> 5;
    const int n = blockIdx.z, co0 = blockIdx.y * 128, p0 = blockIdx.x * 128;
    const int m0 = (wid & 3) * 32, n0w = (wid >> 2) * 64;
    const int mtw = (wid & 3) * 2;          // first local m-tile (of 8 in CTA)

    // staging geometry for B (row validity -> zfill)
    const int sr = tid >> 1, shalf = tid & 1;
    const int sp = p0 + sr;
    const int sh = sp / 56, sw = sp - sh * 56;

    float acc[2][8][4];
    #pragma unroll
    for (int i = 0; i < 2; i++)
        #pragma unroll
        for (int j = 0; j < 8; j++)
            #pragma unroll
            for (int k = 0; k < 4; k++) acc[i][j][k] = 0.f;

    auto issue = [&](int c) {
        int tap = c >> 2, cb = c & 3;
        int dh = (tap / 5) * 3 - 6, dw = (tap % 5) * 3 - 6;
        long long q0 = (long long)p0 + dh * 56 + dw;
        uint32_t dst = smb + (uint32_t)(c & 1) * BUFSZ;

        // A: 32KB contiguous fragment-order block, 128B per thread
        const char* as = (const char*)g_Wt
            + (size_t)(tap * 4 + cb) * 65536 + (size_t)blockIdx.y * 32768 + tid * 128;
        uint32_t ad = dst + (uint32_t)tid * 128u;
        #pragma unroll
        for (int j = 0; j < 8; j++) CPA16(ad + j * 16, as + j * 16);

        // B: 128 rows x 256B; 128B per thread; invalid rows -> zfill
        int ih = sh + dh, iw = sw + dw;
        uint32_t ssz = ((sp < HWP) && ((unsigned)ih < 56u) && ((unsigned)iw < 56u)) ? 16u : 0u;
        const char* bs = (const char*)g_xt +
            (size_t)((long long)(n * 4 + cb) * HWP + q0 + sr + XPAD) * 256 + shalf * 128;
        uint32_t bd = dst + 32768u + (uint32_t)sr * 256u + (uint32_t)shalf * 128u;
        #pragma unroll
        for (int j = 0; j < 8; j++) CPA16Z(bd + j * 16, bs + j * 16, ssz);
        asm volatile("cp.async.commit_group;" ::: "memory");
    };

    issue(0);

    for (int c = 0; c < 100; c++) {
        const uint32_t buf = smb + (uint32_t)(c & 1) * BUFSZ;
        const int tap = c >> 2;
        const int dh = (tap / 5) * 3 - 6, dw = (tap % 5) * 3 - 6;
        const int q0m = ((p0 + dh * 56 + dw) % 8 + 8) & 7;

        if (c + 1 < 100) {
            issue(c + 1);
            asm volatile("cp.async.wait_group 1;" ::: "memory");
        } else {
            asm volatile("cp.async.wait_group 0;" ::: "memory");
        }
        __syncthreads();

        const uint32_t bufB = buf + 32768u;
        const int qrl = lane >> 2;                  // B-row within each 8-group
        const uint32_t browb = bufB + (uint32_t)((n0w + qrl) * 256) + (uint32_t)(lane & 3) * 8u;

        #pragma unroll
        for (int ks = 0; ks < 8; ks++) {
            // A fragments: one LDS.128 per m-tile
            uint32_t af[2][4];
            #pragma unroll
            for (int mi = 0; mi < 2; mi++) {
                uint32_t ad = buf + (uint32_t)((((mtw + mi) * 8 + ks) * 32 + lane) * 16);
                LDS128(af[mi], ad);
            }
            // B slot group for this k-step (independent of n-tile)
            const uint32_t soff = (uint32_t)(((ks + q0m + qrl) & 7) * 32);
            #pragma unroll
            for (int nj = 0; nj < 8; nj++) {
                uint32_t bf[2];
                LDS64(bf, browb + (uint32_t)(nj * 8 * 256) + soff);
                mma_tf32(acc[0][nj], af[0], bf);
                mma_tf32(acc[1][nj], af[1], bf);
            }
        }
        __syncthreads();
    }

    // ---- fused epilogue: out = t1 - (t9*roll(x) + x*t7) ----
    const int er = lane >> 2, ec = (lane & 3) * 2;
    const float* xn = x + n * CHW;
    #pragma unroll
    for (int mi = 0; mi < 2; mi++) {
        #pragma unroll
        for (int rr = 0; rr < 2; rr++) {
            int co = co0 + m0 + mi * 16 + rr * 8 + er;
            const float* xc  = xn + co * HWP;
            const float* t1r = g_t1 + (n * 256 + co) * 56;
            float* oc = out + (n * 256 + co) * HWP;
            #pragma unroll
            for (int nj = 0; nj < 8; nj++) {
                #pragma unroll
                for (int e = 0; e < 2; e++) {
                    int p = p0 + n0w + nj * 8 + ec + e;
                    if (p < HWP) {
                        int h = p / 56, w = p - h * 56;
                        int hr = h - 2; if (hr < 0) hr += 56;
                        float dv  = acc[mi][nj][rr * 2 + e];
                        float xv  = xc[p];
                        float xrl = xc[hr * 56 + w];
                        oc[p] = t1r[h] - (g_t9[n * HWP + p] * xrl + xv * dv);
                    }
                }
            }
        }
    }
}

// ---------------------------------------------------------------------------
extern "C" void kernel_launch(void* const* d_in, const int* in_sizes, int n_in,
                              void* d_out, int out_size) {
    const float* x  = (const float*)d_in[0];
    const float* w6 = (const float*)d_in[1];
    const float* w7 = (const float*)d_in[2];
    float* out = (float*)d_out;

    cudaFuncSetAttribute(conv_tf32_kernel,
                         cudaFuncAttributeMaxDynamicSharedMemorySize, SMEM_CONV);

    split_w_kernel<<<25 * 4 * 16 * 8 * 32 / 256, 256>>>(w7);
    split_x_kernel<<<dim3(HWP / 32, 4, NB), 256>>>(x);
    rowmax_kernel<<<NB * CC * HH / 4, 128>>>(x);
    softmax_kernel<<<dim3(HH / 4, NB), 256>>>(x, w6);
    conv_tf32_kernel<<<dim3(25, 2, NB), 256, SMEM_CONV>>>(x, out);
}

// round 15
// speedup vs baseline: 1.8210x; 1.8021x over previous
#include <cuda_runtime.h>
#include <cuda_fp16.h>
#include <math.h>
#include <stdint.h>

// Problem constants
#define NB   32
#define CC   256
#define HH   56
#define WW   56
#define HWP  3136      // 56*56
#define CHW  802816    // 256*3136
#define XPAD 512       // guard rows (128B each) at both ends of g_x arrays

// ---------------------------------------------------------------------------
// Device-global scratch (no allocation).
// g_x{h,l}: x as fp16 hi/lo, rows [(n*4+cb)*HWP + q + XPAD] of 64 ci,
//           128B rows, 16B chunk ch stored at position ch ^ (q&7).
// g_Wh:     weights as single fp16, rows [(tap*4+cb)*256 + co] of 64 ci,
//           chunk ^ (co&7).
// ---------------------------------------------------------------------------
#define XROWS ((size_t)NB * 4 * HWP + 2 * XPAD)
__device__ __align__(128) __half g_xh[XROWS * 64];
__device__ __align__(128) __half g_xl[XROWS * 64];
__device__ __align__(128) __half g_Wh[25 * 4 * 256 * 64];
__device__ float g_t1[NB * CC * HH];      // max over W
__device__ float g_t9[NB * HH * WW];      // softmax weights

// ---------------------------------------------------------------------------
// Helpers
// ---------------------------------------------------------------------------
__device__ __forceinline__ uint32_t smem_u32(const void* p) {
    uint32_t a;
    asm("{ .reg .u64 t; cvta.to.shared.u64 t, %1; cvt.u32.u64 %0, t; }" : "=r"(a) : "l"(p));
    return a;
}

__device__ __forceinline__ void split1h(float v, __half& h, __half& l) {
    h = __float2half_rn(v);
    l = __float2half_rn(v - __half2float(h));
}

__device__ __forceinline__ void split2h(float a, float b, uint32_t& hw, uint32_t& lw) {
    __half h0, l0, h1, l1;
    split1h(a, h0, l0); split1h(b, h1, l1);
    hw = (uint32_t)__half_as_ushort(h0) | ((uint32_t)__half_as_ushort(h1) << 16);
    lw = (uint32_t)__half_as_ushort(l0) | ((uint32_t)__half_as_ushort(l1) << 16);
}

__device__ __forceinline__ void mma16816(float* d, const uint32_t* a, const uint32_t* b) {
    asm volatile("mma.sync.aligned.m16n8k16.row.col.f32.f16.f16.f32 "
        "{%0,%1,%2,%3}, {%4,%5,%6,%7}, {%8,%9}, {%0,%1,%2,%3};"
        : "+f"(d[0]), "+f"(d[1]), "+f"(d[2]), "+f"(d[3])
        : "r"(a[0]), "r"(a[1]), "r"(a[2]), "r"(a[3]), "r"(b[0]), "r"(b[1]));
}

#define LDSM4(r, a)                                                              \
    asm volatile("ldmatrix.sync.aligned.m8n8.x4.shared.b16 {%0,%1,%2,%3}, [%4];" \
        : "=r"((r)[0]), "=r"((r)[1]), "=r"((r)[2]), "=r"((r)[3]) : "r"(a))

#define CPA16(d, s) \
    asm volatile("cp.async.cg.shared.global [%0], [%1], 16;" :: "r"(d), "l"(s) : "memory")

// cp.async with src-size: z==0 -> pure zero-fill of the 16B destination
#define CPA16Z(d, s, z) \
    asm volatile("cp.async.cg.shared.global [%0], [%1], 16, %2;" :: "r"(d), "l"(s), "r"(z) : "memory")

// ---------------------------------------------------------------------------
// 1) Weight relayout: w7 -> single fp16, rows of 64 ci, chunk ^ (co&7)
// ---------------------------------------------------------------------------
__global__ void split_w_kernel(const float* __restrict__ w7) {
    int idx = blockIdx.x * 256 + threadIdx.x;   // 25*4*256*64 = 1,638,400 exact
    int cl  = idx & 63;
    int co  = (idx >> 6) & 255;
    int cb  = (idx >> 14) & 3;
    int tap = idx >> 16;
    float v = w7[co * 6400 + (cb * 64 + cl) * 25 + tap];
    int ch = cl >> 3, wi = cl & 7;
    size_t dst = ((size_t)((tap * 4 + cb) * 256 + co)) * 64 + ((ch ^ (co & 7)) << 3) + wi;
    g_Wh[dst] = __float2half_rn(v);
}

// ---------------------------------------------------------------------------
// 2) x split+transpose: [n][c][p] -> fp16 hi/lo rows [(n*4+cb)*HWP + q + XPAD][64ci]
// ---------------------------------------------------------------------------
__global__ void split_x_kernel(const float* __restrict__ x) {
    __shared__ float tile[64][33];
    int n = blockIdx.z, cb = blockIdx.y;
    int q0t = blockIdx.x * 32;
    int tid = threadIdx.x;
    int ln = tid & 31;
    #pragma unroll
    for (int i = 0; i < 8; i++) {
        int cl = (tid >> 5) + i * 8;
        tile[cl][ln] = x[n * CHW + (cb * 64 + cl) * HWP + q0t + ln];
    }
    __syncthreads();
    int ql = tid >> 3, ch = tid & 7;
    int q = q0t + ql;
    int chs = ch ^ (q & 7);
    uint32_t hw[4], lw[4];
    #pragma unroll
    for (int j = 0; j < 4; j++)
        split2h(tile[ch * 8 + j * 2][ql], tile[ch * 8 + j * 2 + 1][ql], hw[j], lw[j]);
    size_t r16 = ((size_t)(n * 4 + cb) * HWP + q + XPAD) * 8 + chs;
    ((uint4*)g_xh)[r16] = make_uint4(hw[0], hw[1], hw[2], hw[3]);
    ((uint4*)g_xl)[r16] = make_uint4(lw[0], lw[1], lw[2], lw[3]);
}

// ---------------------------------------------------------------------------
// 3) t1 = max over W
// ---------------------------------------------------------------------------
__global__ void rowmax_kernel(const float* __restrict__ x) {
    int row  = blockIdx.x * 4 + (threadIdx.x >> 5);
    int lane = threadIdx.x & 31;
    const float* xr = x + row * 56;
    float m = xr[lane];
    if (lane < 24) m = fmaxf(m, xr[lane + 32]);
    #pragma unroll
    for (int o = 16; o > 0; o >>= 1)
        m = fmaxf(m, __shfl_xor_sync(0xffffffffu, m, o));
    if (lane == 0) g_t1[row] = m;
}

// ---------------------------------------------------------------------------
// 4) t9 = softmax_w( sum_c tanh(relu(x)) * w6[c] ); 4 h-rows per 256-thr block
// ---------------------------------------------------------------------------
__global__ void softmax_kernel(const float* __restrict__ x,
                               const float* __restrict__ w6) {
    __shared__ float w6s[256];
    __shared__ float red[4][64];
    int n = blockIdx.y;
    int g = threadIdx.x >> 6, t = threadIdx.x & 63;
    int h = blockIdx.x * 4 + g;
    w6s[threadIdx.x] = w6[threadIdx.x];
    __syncthreads();

    float acc = 0.f;
    if (t < 56) {
        const float* xp = x + (n * 256 * 56 + h) * 56 + t;
        #pragma unroll 4
        for (int c = 0; c < 256; c++) {
            float v = xp[c * HWP];
            float r = fmaxf(v, 0.f);
            float th;
            asm("tanh.approx.f32 %0, %1;" : "=f"(th) : "f"(r));
            acc += th * w6s[c];
        }
    }
    red[g][t] = (t < 56) ? acc : -INFINITY;
    __syncthreads();
    #pragma unroll
    for (int s = 32; s > 0; s >>= 1) {
        if (t < s) red[g][t] = fmaxf(red[g][t], red[g][t + s]);
        __syncthreads();
    }
    float mx = red[g][0];
    __syncthreads();
    float e = (t < 56) ? expf(acc - mx) : 0.f;
    red[g][t] = e;
    __syncthreads();
    #pragma unroll
    for (int s = 32; s > 0; s >>= 1) {
        if (t < s) red[g][t] += red[g][t + s];
        __syncthreads();
    }
    float inv = 1.0f / red[g][0];
    if (t < 56) g_t9[(n * 56 + h) * 56 + t] = e * inv;
}

// ---------------------------------------------------------------------------
// 5) Conv via mma.sync fp16 implicit GEMM, 2 passes (wh*xh + wh*xl),
//    fused epilogue.  CTA: 128 co x 128 px; 8 warps (4M x 2N), tile 32x64.
//    SMEM buf b at b*49152: A 16K | Bh 16K | Bl 16K.  2 CTAs/SM.
// ---------------------------------------------------------------------------
#define BUFSZ 49152u
#define SMEM_CONV (2 * 49152)

__global__ __launch_bounds__(256, 2)
void conv_hmma_kernel(const float* __restrict__ x, float* __restrict__ out) {
    extern __shared__ __align__(128) char sm[];
    const uint32_t smb = smem_u32(sm);
    const int tid = threadIdx.x, lane = tid & 31, wid = tid >> 5;
    const int n = blockIdx.z, co0 = blockIdx.y * 128, p0 = blockIdx.x * 128;
    const int m0 = (wid & 3) * 32, n0w = (wid >> 2) * 64;

    // ldmatrix per-lane geometry (validated R11 mapping)
    const int a_row = ((lane >> 3) & 1) * 8 + (lane & 7);
    const int a_ks  = lane >> 4;
    const int b_row = ((lane >> 4) & 1) * 8 + (lane & 7);
    const int b_ks  = (lane >> 3) & 1;
    const int akey  = lane & 7;

    // staging geometry for B (row validity -> zfill)
    const int sr = tid >> 1, shalf = tid & 1;
    const int sp = p0 + sr;
    const int sh = sp / 56, sw = sp - sh * 56;

    float acc[2][8][4];
    #pragma unroll
    for (int i = 0; i < 2; i++)
        #pragma unroll
        for (int j = 0; j < 8; j++)
            #pragma unroll
            for (int k = 0; k < 4; k++) acc[i][j][k] = 0.f;

    auto issue = [&](int c) {
        int tap = c >> 2, cb = c & 3;
        int dh = (tap / 5) * 3 - 6, dw = (tap % 5) * 3 - 6;
        long long q0 = (long long)p0 + dh * 56 + dw;
        uint32_t dst = smb + (uint32_t)(c & 1) * BUFSZ;

        // A: 16KB (128 co rows x 128B), 64B per thread
        const char* ah = (const char*)g_Wh +
            ((size_t)((tap * 4 + cb) * 256 + co0)) * 128 + tid * 64;
        uint32_t ad = dst + (uint32_t)tid * 64u;
        #pragma unroll
        for (int j = 0; j < 4; j++) CPA16(ad + j * 16, ah + j * 16);

        // B: 128 rows x 128B hi/lo; 64B per thread each; invalid rows -> zfill
        int ih = sh + dh, iw = sw + dw;
        uint32_t ssz = ((sp < HWP) && ((unsigned)ih < 56u) && ((unsigned)iw < 56u)) ? 16u : 0u;
        const char* bh = (const char*)g_xh +
            (size_t)((long long)(n * 4 + cb) * HWP + q0 + sr + XPAD) * 128 + shalf * 64;
        const char* bl = (const char*)g_xl +
            (size_t)((long long)(n * 4 + cb) * HWP + q0 + sr + XPAD) * 128 + shalf * 64;
        uint32_t bd = dst + 16384u + (uint32_t)sr * 128u + (uint32_t)shalf * 64u;
        #pragma unroll
        for (int j = 0; j < 4; j++) {
            CPA16Z(bd + j * 16,           bh + j * 16, ssz);
            CPA16Z(bd + 16384u + j * 16,  bl + j * 16, ssz);
        }
        asm volatile("cp.async.commit_group;" ::: "memory");
    };

    issue(0);

    for (int c = 0; c < 100; c++) {
        const uint32_t buf = smb + (uint32_t)(c & 1) * BUFSZ;
        const int tap = c >> 2;
        const int dh = (tap / 5) * 3 - 6, dw = (tap % 5) * 3 - 6;
        const int q0m = ((p0 + dh * 56 + dw) % 8 + 8) & 7;
        const int bkey = (q0m + b_row) & 7;

        if (c + 1 < 100) {
            issue(c + 1);
            asm volatile("cp.async.wait_group 1;" ::: "memory");
        } else {
            asm volatile("cp.async.wait_group 0;" ::: "memory");
        }
        __syncthreads();

        #pragma unroll
        for (int ks = 0; ks < 4; ks++) {
            uint32_t ah[2][4];
            #pragma unroll
            for (int mi = 0; mi < 2; mi++) {
                uint32_t ad = buf + (uint32_t)((m0 + mi * 16 + a_row) * 128)
                                  + (uint32_t)(((ks * 2 + a_ks) ^ akey) << 4);
                LDSM4(ah[mi], ad);
            }
            #pragma unroll
            for (int nj = 0; nj < 4; nj++) {
                uint32_t bd = buf + 16384u + (uint32_t)((n0w + nj * 16 + b_row) * 128)
                                  + (uint32_t)(((ks * 2 + b_ks) ^ bkey) << 4);
                uint32_t bh4[4], bl4[4];
                LDSM4(bh4, bd);
                LDSM4(bl4, bd + 16384u);
                #pragma unroll
                for (int mi = 0; mi < 2; mi++) {
                    mma16816(acc[mi][nj * 2],     ah[mi], &bh4[0]);
                    mma16816(acc[mi][nj * 2 + 1], ah[mi], &bh4[2]);
                    mma16816(acc[mi][nj * 2],     ah[mi], &bl4[0]);
                    mma16816(acc[mi][nj * 2 + 1], ah[mi], &bl4[2]);
                }
            }
        }
        __syncthreads();
    }

    // ---- fused epilogue: out = t1 - (t9*roll(x) + x*t7) ----
    const int er = lane >> 2, ec = (lane & 3) * 2;
    const float* xn = x + n * CHW;
    #pragma unroll
    for (int mi = 0; mi < 2; mi++) {
        #pragma unroll
        for (int rr = 0; rr < 2; rr++) {
            int co = co0 + m0 + mi * 16 + rr * 8 + er;
            const float* xc  = xn + co * HWP;
            const float* t1r = g_t1 + (n * 256 + co) * 56;
            float* oc = out + (n * 256 + co) * HWP;
            #pragma unroll
            for (int ng = 0; ng < 8; ng++) {
                #pragma unroll
                for (int e = 0; e < 2; e++) {
                    int p = p0 + n0w + ng * 8 + ec + e;
                    if (p < HWP) {
                        int h = p / 56, w = p - h * 56;
                        int hr = h - 2; if (hr < 0) hr += 56;
                        float dv  = acc[mi][ng][rr * 2 + e];
                        float xv  = xc[p];
                        float xrl = xc[hr * 56 + w];
                        oc[p] = t1r[h] - (g_t9[n * HWP + p] * xrl + xv * dv);
                    }
                }
            }
        }
    }
}

// ---------------------------------------------------------------------------
extern "C" void kernel_launch(void* const* d_in, const int* in_sizes, int n_in,
                              void* d_out, int out_size) {
    const float* x  = (const float*)d_in[0];
    const float* w6 = (const float*)d_in[1];
    const float* w7 = (const float*)d_in[2];
    float* out = (float*)d_out;

    cudaFuncSetAttribute(conv_hmma_kernel,
                         cudaFuncAttributeMaxDynamicSharedMemorySize, SMEM_CONV);

    split_w_kernel<<<25 * 4 * 256 * 64 / 256, 256>>>(w7);
    split_x_kernel<<<dim3(HWP / 32, 4, NB), 256>>>(x);
    rowmax_kernel<<<NB * CC * HH / 4, 128>>>(x);
    softmax_kernel<<<dim3(HH / 4, NB), 256>>>(x, w6);
    conv_hmma_kernel<<<dim3(25, 2, NB), 256, SMEM_CONV>>>(x, out);
}

// round 16
// speedup vs baseline: 2.9803x; 1.6366x over previous
#include <cuda_runtime.h>
#include <cuda_fp16.h>
#include <math.h>
#include <stdint.h>

// Problem constants
#define NB   32
#define CC   256
#define HH   56
#define WW   56
#define HWP  3136      // 56*56
#define CHW  802816    // 256*3136
#define XPAD 512       // guard rows (128B each) at both ends of g_xh

// ---------------------------------------------------------------------------
// Device-global scratch (no allocation).
// g_xh: x as fp16, rows [(n*4+cb)*HWP + q + XPAD] of 64 ci,
//       128B rows, 16B chunk ch stored at position ch ^ (q&7).
// g_Wh: weights as fp16, rows [(tap*4+cb)*256 + co] of 64 ci, chunk ^ (co&7).
// ---------------------------------------------------------------------------
#define XROWS ((size_t)NB * 4 * HWP + 2 * XPAD)
__device__ __align__(128) __half g_xh[XROWS * 64];
__device__ __align__(128) __half g_Wh[25 * 4 * 256 * 64];
__device__ float g_t1[NB * CC * HH];      // max over W
__device__ float g_t9[NB * HH * WW];      // softmax weights

// ---------------------------------------------------------------------------
// Helpers
// ---------------------------------------------------------------------------
__device__ __forceinline__ uint32_t smem_u32(const void* p) {
    uint32_t a;
    asm("{ .reg .u64 t; cvta.to.shared.u64 t, %1; cvt.u32.u64 %0, t; }" : "=r"(a) : "l"(p));
    return a;
}

__device__ __forceinline__ uint32_t pack2h(float a, float b) {
    __half h0 = __float2half_rn(a), h1 = __float2half_rn(b);
    return (uint32_t)__half_as_ushort(h0) | ((uint32_t)__half_as_ushort(h1) << 16);
}

__device__ __forceinline__ void mma16816(float* d, const uint32_t* a, const uint32_t* b) {
    asm volatile("mma.sync.aligned.m16n8k16.row.col.f32.f16.f16.f32 "
        "{%0,%1,%2,%3}, {%4,%5,%6,%7}, {%8,%9}, {%0,%1,%2,%3};"
        : "+f"(d[0]), "+f"(d[1]), "+f"(d[2]), "+f"(d[3])
        : "r"(a[0]), "r"(a[1]), "r"(a[2]), "r"(a[3]), "r"(b[0]), "r"(b[1]));
}

#define LDSM4(r, a)                                                              \
    asm volatile("ldmatrix.sync.aligned.m8n8.x4.shared.b16 {%0,%1,%2,%3}, [%4];" \
        : "=r"((r)[0]), "=r"((r)[1]), "=r"((r)[2]), "=r"((r)[3]) : "r"(a))

#define CPA16(d, s) \
    asm volatile("cp.async.cg.shared.global [%0], [%1], 16;" :: "r"(d), "l"(s) : "memory")

// cp.async with src-size: z==0 -> pure zero-fill of the 16B destination
#define CPA16Z(d, s, z) \
    asm volatile("cp.async.cg.shared.global [%0], [%1], 16, %2;" :: "r"(d), "l"(s), "r"(z) : "memory")

// ---------------------------------------------------------------------------
// 1) Weight relayout: w7 -> fp16, rows of 64 ci, chunk ^ (co&7)
// ---------------------------------------------------------------------------
__global__ void split_w_kernel(const float* __restrict__ w7) {
    int idx = blockIdx.x * 256 + threadIdx.x;   // 25*4*256*64 = 1,638,400 exact
    int cl  = idx & 63;
    int co  = (idx >> 6) & 255;
    int cb  = (idx >> 14) & 3;
    int tap = idx >> 16;
    float v = w7[co * 6400 + (cb * 64 + cl) * 25 + tap];
    int ch = cl >> 3, wi = cl & 7;
    size_t dst = ((size_t)((tap * 4 + cb) * 256 + co)) * 64 + ((ch ^ (co & 7)) << 3) + wi;
    g_Wh[dst] = __float2half_rn(v);
}

// ---------------------------------------------------------------------------
// 2) x transpose: [n][c][p] -> fp16 rows [(n*4+cb)*HWP + q + XPAD][64ci]
// ---------------------------------------------------------------------------
__global__ void split_x_kernel(const float* __restrict__ x) {
    __shared__ float tile[64][33];
    int n = blockIdx.z, cb = blockIdx.y;
    int q0t = blockIdx.x * 32;
    int tid = threadIdx.x;
    int ln = tid & 31;
    #pragma unroll
    for (int i = 0; i < 8; i++) {
        int cl = (tid >> 5) + i * 8;
        tile[cl][ln] = x[n * CHW + (cb * 64 + cl) * HWP + q0t + ln];
    }
    __syncthreads();
    int ql = tid >> 3, ch = tid & 7;
    int q = q0t + ql;
    int chs = ch ^ (q & 7);
    uint32_t hw[4];
    #pragma unroll
    for (int j = 0; j < 4; j++)
        hw[j] = pack2h(tile[ch * 8 + j * 2][ql], tile[ch * 8 + j * 2 + 1][ql]);
    size_t r16 = ((size_t)(n * 4 + cb) * HWP + q + XPAD) * 8 + chs;
    ((uint4*)g_xh)[r16] = make_uint4(hw[0], hw[1], hw[2], hw[3]);
}

// ---------------------------------------------------------------------------
// 3) t1 = max over W
// ---------------------------------------------------------------------------
__global__ void rowmax_kernel(const float* __restrict__ x) {
    int row  = blockIdx.x * 4 + (threadIdx.x >> 5);
    int lane = threadIdx.x & 31;
    const float* xr = x + row * 56;
    float m = xr[lane];
    if (lane < 24) m = fmaxf(m, xr[lane + 32]);
    #pragma unroll
    for (int o = 16; o > 0; o >>= 1)
        m = fmaxf(m, __shfl_xor_sync(0xffffffffu, m, o));
    if (lane == 0) g_t1[row] = m;
}

// ---------------------------------------------------------------------------
// 4) t9 = softmax_w( sum_c tanh(relu(x)) * w6[c] ); 4 h-rows per 256-thr block
// ---------------------------------------------------------------------------
__global__ void softmax_kernel(const float* __restrict__ x,
                               const float* __restrict__ w6) {
    __shared__ float w6s[256];
    __shared__ float red[4][64];
    int n = blockIdx.y;
    int g = threadIdx.x >> 6, t = threadIdx.x & 63;
    int h = blockIdx.x * 4 + g;
    w6s[threadIdx.x] = w6[threadIdx.x];
    __syncthreads();

    float acc = 0.f;
    if (t < 56) {
        const float* xp = x + (n * 256 * 56 + h) * 56 + t;
        #pragma unroll 4
        for (int c = 0; c < 256; c++) {
            float v = xp[c * HWP];
            float r = fmaxf(v, 0.f);
            float th;
            asm("tanh.approx.f32 %0, %1;" : "=f"(th) : "f"(r));
            acc += th * w6s[c];
        }
    }
    red[g][t] = (t < 56) ? acc : -INFINITY;
    __syncthreads();
    #pragma unroll
    for (int s = 32; s > 0; s >>= 1) {
        if (t < s) red[g][t] = fmaxf(red[g][t], red[g][t + s]);
        __syncthreads();
    }
    float mx = red[g][0];
    __syncthreads();
    float e = (t < 56) ? expf(acc - mx) : 0.f;
    red[g][t] = e;
    __syncthreads();
    #pragma unroll
    for (int s = 32; s > 0; s >>= 1) {
        if (t < s) red[g][t] += red[g][t + s];
        __syncthreads();
    }
    float inv = 1.0f / red[g][0];
    if (t < 56) g_t9[(n * 56 + h) * 56 + t] = e * inv;
}

// ---------------------------------------------------------------------------
// 5) Conv via mma.sync fp16 implicit GEMM, SINGLE pass (wh*xh),
//    fused epilogue.  CTA: 128 co x 128 px; 8 warps (4M x 2N), tile 32x64.
//    SMEM buf b at b*32768: A 16K | B 16K.  2 CTAs/SM.
// ---------------------------------------------------------------------------
#define BUFSZ 32768u
#define SMEM_CONV (2 * 32768)

__global__ __launch_bounds__(256, 2)
void conv_hmma_kernel(const float* __restrict__ x, float* __restrict__ out) {
    extern __shared__ __align__(128) char sm[];
    const uint32_t smb = smem_u32(sm);
    const int tid = threadIdx.x, lane = tid & 31, wid = tid >> 5;
    const int n = blockIdx.z, co0 = blockIdx.y * 128, p0 = blockIdx.x * 128;
    const int m0 = (wid & 3) * 32, n0w = (wid >> 2) * 64;

    // ldmatrix per-lane geometry (validated R11 mapping)
    const int a_row = ((lane >> 3) & 1) * 8 + (lane & 7);
    const int a_ks  = lane >> 4;
    const int b_row = ((lane >> 4) & 1) * 8 + (lane & 7);
    const int b_ks  = (lane >> 3) & 1;
    const int akey  = lane & 7;

    // staging geometry for B (row validity -> zfill)
    const int sr = tid >> 1, shalf = tid & 1;
    const int sp = p0 + sr;
    const int sh = sp / 56, sw = sp - sh * 56;

    float acc[2][8][4];
    #pragma unroll
    for (int i = 0; i < 2; i++)
        #pragma unroll
        for (int j = 0; j < 8; j++)
            #pragma unroll
            for (int k = 0; k < 4; k++) acc[i][j][k] = 0.f;

    auto issue = [&](int c) {
        int tap = c >> 2, cb = c & 3;
        int dh = (tap / 5) * 3 - 6, dw = (tap % 5) * 3 - 6;
        long long q0 = (long long)p0 + dh * 56 + dw;
        uint32_t dst = smb + (uint32_t)(c & 1) * BUFSZ;

        // A: 16KB (128 co rows x 128B), 64B per thread
        const char* ah = (const char*)g_Wh +
            ((size_t)((tap * 4 + cb) * 256 + co0)) * 128 + tid * 64;
        uint32_t ad = dst + (uint32_t)tid * 64u;
        #pragma unroll
        for (int j = 0; j < 4; j++) CPA16(ad + j * 16, ah + j * 16);

        // B: 128 rows x 128B; 64B per thread; invalid rows -> zfill
        int ih = sh + dh, iw = sw + dw;
        uint32_t ssz = ((sp < HWP) && ((unsigned)ih < 56u) && ((unsigned)iw < 56u)) ? 16u : 0u;
        const char* bh = (const char*)g_xh +
            (size_t)((long long)(n * 4 + cb) * HWP + q0 + sr + XPAD) * 128 + shalf * 64;
        uint32_t bd = dst + 16384u + (uint32_t)sr * 128u + (uint32_t)shalf * 64u;
        #pragma unroll
        for (int j = 0; j < 4; j++) CPA16Z(bd + j * 16, bh + j * 16, ssz);
        asm volatile("cp.async.commit_group;" ::: "memory");
    };

    issue(0);

    for (int c = 0; c < 100; c++) {
        const uint32_t buf = smb + (uint32_t)(c & 1) * BUFSZ;
        const int tap = c >> 2;
        const int dh = (tap / 5) * 3 - 6, dw = (tap % 5) * 3 - 6;
        const int q0m = ((p0 + dh * 56 + dw) % 8 + 8) & 7;
        const int bkey = (q0m + b_row) & 7;

        if (c + 1 < 100) {
            issue(c + 1);
            asm volatile("cp.async.wait_group 1;" ::: "memory");
        } else {
            asm volatile("cp.async.wait_group 0;" ::: "memory");
        }
        __syncthreads();

        #pragma unroll
        for (int ks = 0; ks < 4; ks++) {
            uint32_t ah[2][4];
            #pragma unroll
            for (int mi = 0; mi < 2; mi++) {
                uint32_t ad = buf + (uint32_t)((m0 + mi * 16 + a_row) * 128)
                                  + (uint32_t)(((ks * 2 + a_ks) ^ akey) << 4);
                LDSM4(ah[mi], ad);
            }
            #pragma unroll
            for (int nj = 0; nj < 4; nj++) {
                uint32_t bd = buf + 16384u + (uint32_t)((n0w + nj * 16 + b_row) * 128)
                                  + (uint32_t)(((ks * 2 + b_ks) ^ bkey) << 4);
                uint32_t bh4[4];
                LDSM4(bh4, bd);
                #pragma unroll
                for (int mi = 0; mi < 2; mi++) {
                    mma16816(acc[mi][nj * 2],     ah[mi], &bh4[0]);
                    mma16816(acc[mi][nj * 2 + 1], ah[mi], &bh4[2]);
                }
            }
        }
        __syncthreads();
    }

    // ---- fused epilogue: out = t1 - (t9*roll(x) + x*t7) ----
    const int er = lane >> 2, ec = (lane & 3) * 2;
    const float* xn = x + n * CHW;
    #pragma unroll
    for (int mi = 0; mi < 2; mi++) {
        #pragma unroll
        for (int rr = 0; rr < 2; rr++) {
            int co = co0 + m0 + mi * 16 + rr * 8 + er;
            const float* xc  = xn + co * HWP;
            const float* t1r = g_t1 + (n * 256 + co) * 56;
            float* oc = out + (n * 256 + co) * HWP;
            #pragma unroll
            for (int ng = 0; ng < 8; ng++) {
                #pragma unroll
                for (int e = 0; e < 2; e++) {
                    int p = p0 + n0w + ng * 8 + ec + e;
                    if (p < HWP) {
                        int h = p / 56, w = p - h * 56;
                        int hr = h - 2; if (hr < 0) hr += 56;
                        float dv  = acc[mi][ng][rr * 2 + e];
                        float xv  = xc[p];
                        float xrl = xc[hr * 56 + w];
                        oc[p] = t1r[h] - (g_t9[n * HWP + p] * xrl + xv * dv);
                    }
                }
            }
        }
    }
}

// ---------------------------------------------------------------------------
extern "C" void kernel_launch(void* const* d_in, const int* in_sizes, int n_in,
                              void* d_out, int out_size) {
    const float* x  = (const float*)d_in[0];
    const float* w6 = (const float*)d_in[1];
    const float* w7 = (const float*)d_in[2];
    float* out = (float*)d_out;

    cudaFuncSetAttribute(conv_hmma_kernel,
                         cudaFuncAttributeMaxDynamicSharedMemorySize, SMEM_CONV);

    split_w_kernel<<<25 * 4 * 256 * 64 / 256, 256>>>(w7);
    split_x_kernel<<<dim3(HWP / 32, 4, NB), 256>>>(x);
    rowmax_kernel<<<NB * CC * HH / 4, 128>>>(x);
    softmax_kernel<<<dim3(HH / 4, NB), 256>>>(x, w6);
    conv_hmma_kernel<<<dim3(25, 2, NB), 256, SMEM_CONV>>>(x, out);
}